// round 7
// baseline (speedup 1.0000x reference)
#include <cuda_runtime.h>
#include <cuda_bf16.h>

// Problem constants
#define BB   4
#define CC   256
#define HH   128
#define WW   128
#define KK   1000
#define POOLED 7
#define NBIN (POOLED*POOLED)          // 49
#define PER_ROI (CC*NBIN)             // 12544 floats per ROI
#define HWSZ (HH*WW)

// Device scratch (sanctioned no-alloc workaround)
__device__ float g_tfeat[BB * HH * WW * CC];   // 64 MB NHWC features
__device__ float g_tmp[KK * PER_ROI];          // 50 MB bin-major ROI output

// ---------------------------------------------------------------------------
// Kernel 1: NCHW -> NHWC transpose, float4 on both global sides.
// ---------------------------------------------------------------------------
__global__ void nchw_to_nhwc(const float* __restrict__ f) {
    __shared__ float tile[32][33];
    const int i  = threadIdx.x;
    const int x0 = blockIdx.x * 32;
    const int c0 = blockIdx.y * 32;
    const int bz = blockIdx.z;
    const int b  = bz >> 7;
    const int y  = bz & 127;

    {   // read (c-row, 4 x) coalesced
        const int cl = i >> 3;
        const int xq = i & 7;
        const float4 v = *(const float4*)(f +
            (((size_t)(b * CC + c0 + cl) * HH + y) * WW + x0 + 4 * xq));
        tile[cl][4 * xq + 0] = v.x;
        tile[cl][4 * xq + 1] = v.y;
        tile[cl][4 * xq + 2] = v.z;
        tile[cl][4 * xq + 3] = v.w;
    }
    __syncthreads();
    {   // gather 4 channels for one x, write float4 coalesced
        const int xl = i >> 3;
        const int cq = i & 7;
        float4 w;
        w.x = tile[4 * cq + 0][xl];
        w.y = tile[4 * cq + 1][xl];
        w.z = tile[4 * cq + 2][xl];
        w.w = tile[4 * cq + 3][xl];
        *(float4*)(g_tfeat +
            (((size_t)(b * HH + y) * WW + x0 + xl) * CC + c0 + 4 * cq)) = w;
    }
}

// ---------------------------------------------------------------------------
// Kernel 2: ROI gather. 256-thread CTA = 4 ROI groups of 64 threads.
// Lane c owns channels [4c, 4c+4): every tap is one float4 load from the
// NHWC scratch. Output written BIN-MAJOR to g_tmp (per bin: 64 lanes store
// a fully coalesced 1KB float4 row). No big smem -> occupancy + full L1D.
// ---------------------------------------------------------------------------
template<int GH, int GW>
__device__ __forceinline__ void roi_body(
    int c, const float* __restrict__ base,
    const int* __restrict__ sxl, const int* __restrict__ sxh,
    const float* __restrict__ slx, const float* __restrict__ shx,
    const int* __restrict__ syl, const int* __restrict__ syh,
    const float* __restrict__ sly, const float* __restrict__ shy,
    float* __restrict__ tmpout)
{
    const float invn = 1.0f / (float)(GH * GW);
#pragma unroll
    for (int py = 0; py < POOLED; ++py) {
        const float* rlo[GH];
        const float* rhi[GH];
        float why[GH], wly[GH];
#pragma unroll
        for (int iy = 0; iy < GH; ++iy) {
            const int ys = py * 2 + iy;
            rlo[iy] = base + syl[ys] * (WW * CC);
            rhi[iy] = base + syh[ys] * (WW * CC);
            why[iy] = shy[ys];
            wly[iy] = sly[ys];
        }
#pragma unroll
        for (int px = 0; px < POOLED; ++px) {
            float ax = 0.f, ay = 0.f, az = 0.f, aw = 0.f;
#pragma unroll
            for (int jx = 0; jx < GW; ++jx) {
                const int xs = px * 2 + jx;
                const int xl = sxl[xs] * CC;
                const int xh = sxh[xs] * CC;
                const float lx = slx[xs];
                const float hx = shx[xs];
#pragma unroll
                for (int iy = 0; iy < GH; ++iy) {
                    const float4 v00 = __ldg((const float4*)(rlo[iy] + xl));
                    const float4 v01 = __ldg((const float4*)(rlo[iy] + xh));
                    const float4 v10 = __ldg((const float4*)(rhi[iy] + xl));
                    const float4 v11 = __ldg((const float4*)(rhi[iy] + xh));
                    const float w00 = why[iy] * hx;
                    const float w01 = why[iy] * lx;
                    const float w10 = wly[iy] * hx;
                    const float w11 = wly[iy] * lx;
                    ax += w00 * v00.x + w01 * v01.x + w10 * v10.x + w11 * v11.x;
                    ay += w00 * v00.y + w01 * v01.y + w10 * v10.y + w11 * v11.y;
                    az += w00 * v00.z + w01 * v01.z + w10 * v10.z + w11 * v11.z;
                    aw += w00 * v00.w + w01 * v01.w + w10 * v10.w + w11 * v11.w;
                }
            }
            const int bin = py * POOLED + px;
            ((float4*)(tmpout + bin * CC))[c] =
                make_float4(ax * invn, ay * invn, az * invn, aw * invn);
        }
    }
}

__global__ void __launch_bounds__(256, 3)
roi_gather_kernel(const float* __restrict__ boxes) {
    __shared__ int   sxl[4][14], sxh[4][14], syl[4][14], syh[4][14];
    __shared__ float slx[4][14], shx[4][14], sly[4][14], shy[4][14];

    const int tid = threadIdx.x;
    const int g   = tid >> 6;          // ROI group within CTA
    const int c   = tid & 63;          // channel quad
    const int k   = blockIdx.x * 4 + g;

    // Per-group table precompute: 112 threads cover 4 groups x 28 entries
    if (tid < 112) {
        const int gg = tid / 28;
        const int e  = tid % 28;
        const int kk = blockIdx.x * 4 + gg;
        const float x1 = __ldg(boxes + kk * 5 + 1) * 0.25f;
        const float y1 = __ldg(boxes + kk * 5 + 2) * 0.25f;
        const float x2 = __ldg(boxes + kk * 5 + 3) * 0.25f;
        const float y2 = __ldg(boxes + kk * 5 + 4) * 0.25f;
        const float roi_w = fmaxf(x2 - x1, 1.0f);
        const float roi_h = fmaxf(y2 - y1, 1.0f);

        const bool isy = e >= 14;
        const int  s   = isy ? e - 14 : e;
        const int  p   = s >> 1;
        const int  i   = s & 1;
        const float start = isy ? y1 : x1;
        const float rs    = isy ? roi_h : roi_w;
        const float bs    = rs * (1.0f / POOLED);
        const int   gq    = (int)ceilf(rs * (1.0f / POOLED));
        const float coord = start + (float)p * bs + ((float)i + 0.5f) * bs / (float)gq;

        const bool valid = (coord >= -1.0f) && (coord <= 128.0f);
        float cc = fmaxf(coord, 0.0f);
        int lo = min((int)cc, 127);
        int hi = min(lo + 1, 127);
        float l = (lo >= 127) ? 0.0f : (cc - (float)lo);
        float h = 1.0f - l;
        if (!valid) { l = 0.0f; h = 0.0f; }
        if (isy) { syl[gg][s] = lo; syh[gg][s] = hi; sly[gg][s] = l; shy[gg][s] = h; }
        else     { sxl[gg][s] = lo; sxh[gg][s] = hi; slx[gg][s] = l; shx[gg][s] = h; }
    }
    __syncthreads();

    const int b = (int)__ldg(boxes + k * 5 + 0);
    const float roi_w = fmaxf((__ldg(boxes + k*5+3) - __ldg(boxes + k*5+1)) * 0.25f, 1.0f);
    const float roi_h = fmaxf((__ldg(boxes + k*5+4) - __ldg(boxes + k*5+2)) * 0.25f, 1.0f);
    const int gw2 = min((int)ceilf(roi_w * (1.0f / POOLED)), 2);
    const int gh2 = min((int)ceilf(roi_h * (1.0f / POOLED)), 2);

    const float* base = g_tfeat + (size_t)b * (HWSZ * CC) + 4 * c;
    float* tmpout = g_tmp + (size_t)k * PER_ROI;

    // Warp-uniform dispatch (64-thread groups = whole warps)
    if (gh2 == 1) {
        if (gw2 == 1) roi_body<1,1>(c, base, sxl[g], sxh[g], slx[g], shx[g], syl[g], syh[g], sly[g], shy[g], tmpout);
        else          roi_body<1,2>(c, base, sxl[g], sxh[g], slx[g], shx[g], syl[g], syh[g], sly[g], shy[g], tmpout);
    } else {
        if (gw2 == 1) roi_body<2,1>(c, base, sxl[g], sxh[g], slx[g], shx[g], syl[g], syh[g], sly[g], shy[g], tmpout);
        else          roi_body<2,2>(c, base, sxl[g], sxh[g], slx[g], shx[g], syl[g], syh[g], sly[g], shy[g], tmpout);
    }
}

// ---------------------------------------------------------------------------
// Kernel 3: per-ROI permute [49][256] -> [256][49], coalesced both sides.
// smem layout [bin][260] -> STS.128 conflict-free on load, read-stride 260.
// ---------------------------------------------------------------------------
#define PSTR 260
__global__ void permute_kernel(float* __restrict__ out) {
    extern __shared__ float s[];               // 49*260 floats
    const int k   = blockIdx.x;
    const int tid = threadIdx.x;

    const float4* src = (const float4*)(g_tmp + (size_t)k * PER_ROI);
#pragma unroll 4
    for (int j = tid; j < PER_ROI / 4; j += 256) {
        const float4 v = src[j];
        const int bin = j >> 6;                // (4j)/256
        const int cb  = (j & 63) * 4;          // channel base
        *(float4*)(s + bin * PSTR + cb) = v;   // 16B-aligned (PSTR%4==0)
    }
    __syncthreads();

    float* dst = out + (size_t)k * PER_ROI;
#pragma unroll 4
    for (int i = tid; i < PER_ROI; i += 256) {
        const int ch  = i / NBIN;
        const int bin = i - ch * NBIN;
        dst[i] = s[bin * PSTR + ch];
    }
}

extern "C" void kernel_launch(void* const* d_in, const int* in_sizes, int n_in,
                              void* d_out, int out_size) {
    const float* features = (const float*)d_in[0];   // [4,256,128,128]
    const float* boxes    = (const float*)d_in[1];   // [1000,5]
    float* out = (float*)d_out;                      // [1000,256,7,7]
    (void)in_sizes; (void)n_in; (void)out_size;

    cudaFuncSetAttribute(permute_kernel,
                         cudaFuncAttributeMaxDynamicSharedMemorySize,
                         NBIN * PSTR * (int)sizeof(float));

    // 1) NCHW -> NHWC scratch
    dim3 gT(WW / 32, CC / 32, BB * HH);
    nchw_to_nhwc<<<gT, 256>>>(features);

    // 2) Gather: 4 ROIs per CTA, bin-major output
    roi_gather_kernel<<<KK / 4, 256>>>(boxes);

    // 3) Permute to [K][C][7][7]
    permute_kernel<<<KK, 256, NBIN * PSTR * (int)sizeof(float)>>>(out);
}

// round 8
// speedup vs baseline: 2.0780x; 2.0780x over previous
#include <cuda_runtime.h>
#include <cuda_bf16.h>

// Problem constants
#define BB   4
#define CC   256
#define HH   128
#define WW   128
#define KK   1000
#define POOLED 7
#define NBIN (POOLED*POOLED)          // 49
#define PER_ROI (CC*NBIN)             // 12544 floats per ROI
#define HWSZ (HH*WW)
#define PSTR 260                      // smem staging row stride (floats), %4==0

// 64 MB NHWC scratch (device global: the sanctioned no-alloc workaround)
__device__ float g_tfeat[BB * HH * WW * CC];

// ---------------------------------------------------------------------------
// Kernel 1: NCHW -> NHWC transpose, float4 on both global sides.
// ---------------------------------------------------------------------------
__global__ void nchw_to_nhwc(const float* __restrict__ f) {
    __shared__ float tile[32][33];
    const int i  = threadIdx.x;
    const int x0 = blockIdx.x * 32;
    const int c0 = blockIdx.y * 32;
    const int bz = blockIdx.z;
    const int b  = bz >> 7;
    const int y  = bz & 127;

    {   // read (c-row, 4 x) coalesced
        const int cl = i >> 3;
        const int xq = i & 7;
        const float4 v = *(const float4*)(f +
            (((size_t)(b * CC + c0 + cl) * HH + y) * WW + x0 + 4 * xq));
        tile[cl][4 * xq + 0] = v.x;
        tile[cl][4 * xq + 1] = v.y;
        tile[cl][4 * xq + 2] = v.z;
        tile[cl][4 * xq + 3] = v.w;
    }
    __syncthreads();
    {   // gather 4 channels for one x, write float4 coalesced
        const int xl = i >> 3;
        const int cq = i & 7;
        float4 w;
        w.x = tile[4 * cq + 0][xl];
        w.y = tile[4 * cq + 1][xl];
        w.z = tile[4 * cq + 2][xl];
        w.w = tile[4 * cq + 3][xl];
        *(float4*)(g_tfeat +
            (((size_t)(b * HH + y) * WW + x0 + xl) * CC + c0 + 4 * cq)) = w;
    }
}

// ---------------------------------------------------------------------------
// Kernel 2: fused ROI align. One CTA per ROI, 256 threads =
// 4 bin-groups x 64 channel-quad lanes. Every tap is a float4 load from
// NHWC scratch; results staged in smem (conflict-free STS.128), then
// written to out[k][c][bin] fully coalesced.
// ---------------------------------------------------------------------------
template<int GH, int GW>
__device__ __forceinline__ void process_bin(
    int bin, int c, const float* __restrict__ base, float invn,
    const int* __restrict__ sxl, const int* __restrict__ sxh,
    const float* __restrict__ slx, const float* __restrict__ shx,
    const int* __restrict__ syl, const int* __restrict__ syh,
    const float* __restrict__ sly, const float* __restrict__ shy,
    float* __restrict__ so)
{
    const int py = bin / POOLED;
    const int px = bin - py * POOLED;
    float ax = 0.f, ay = 0.f, az = 0.f, aw = 0.f;
#pragma unroll
    for (int iy = 0; iy < GH; ++iy) {
        const int ys = py * 2 + iy;
        const float* rl = base + syl[ys] * (WW * CC);
        const float* rh = base + syh[ys] * (WW * CC);
        const float hy = shy[ys];
        const float ly = sly[ys];
#pragma unroll
        for (int jx = 0; jx < GW; ++jx) {
            const int xs = px * 2 + jx;
            const int xl = sxl[xs] * CC;
            const int xh = sxh[xs] * CC;
            const float w00 = hy * shx[xs];
            const float w01 = hy * slx[xs];
            const float w10 = ly * shx[xs];
            const float w11 = ly * slx[xs];
            const float4 v00 = __ldg((const float4*)(rl + xl));
            const float4 v01 = __ldg((const float4*)(rl + xh));
            const float4 v10 = __ldg((const float4*)(rh + xl));
            const float4 v11 = __ldg((const float4*)(rh + xh));
            ax += w00 * v00.x + w01 * v01.x + w10 * v10.x + w11 * v11.x;
            ay += w00 * v00.y + w01 * v01.y + w10 * v10.y + w11 * v11.y;
            az += w00 * v00.z + w01 * v01.z + w10 * v10.z + w11 * v11.z;
            aw += w00 * v00.w + w01 * v01.w + w10 * v10.w + w11 * v11.w;
        }
    }
    *(float4*)(so + bin * PSTR + 4 * c) =
        make_float4(ax * invn, ay * invn, az * invn, aw * invn);
}

template<int GH, int GW>
__device__ __forceinline__ void roi_body(
    int g, int c, const float* __restrict__ base,
    const int* __restrict__ sxl, const int* __restrict__ sxh,
    const float* __restrict__ slx, const float* __restrict__ shx,
    const int* __restrict__ syl, const int* __restrict__ syh,
    const float* __restrict__ sly, const float* __restrict__ shy,
    float* __restrict__ so)
{
    const float invn = 1.0f / (float)(GH * GW);
    const int start = 12 * g;
#pragma unroll
    for (int j = 0; j < 12; ++j) {
        process_bin<GH, GW>(start + j, c, base, invn,
                            sxl, sxh, slx, shx, syl, syh, sly, shy, so);
    }
    if (g == 0) {   // leftover bin 48 (warp-uniform branch)
        process_bin<GH, GW>(48, c, base, invn,
                            sxl, sxh, slx, shx, syl, syh, sly, shy, so);
    }
}

__global__ void __launch_bounds__(256, 3)
roi_align_kernel(const float* __restrict__ boxes, float* __restrict__ out) {
    extern __shared__ float so[];            // NBIN*PSTR floats = 50960 B
    __shared__ int   sxl[14], sxh[14], syl[14], syh[14];
    __shared__ float slx[14], shx[14], sly[14], shy[14];

    const int k   = blockIdx.x;
    const int tid = threadIdx.x;
    const int g   = tid >> 6;      // bin group
    const int c   = tid & 63;      // channel quad

    // Per-axis sample tables: entries s = p*2 + i  (p=bin, i=grid idx)
    if (tid < 28) {
        const float x1 = __ldg(boxes + k * 5 + 1) * 0.25f;
        const float y1 = __ldg(boxes + k * 5 + 2) * 0.25f;
        const float x2 = __ldg(boxes + k * 5 + 3) * 0.25f;
        const float y2 = __ldg(boxes + k * 5 + 4) * 0.25f;
        const float roi_w = fmaxf(x2 - x1, 1.0f);
        const float roi_h = fmaxf(y2 - y1, 1.0f);

        const bool isy = tid >= 14;
        const int  s   = isy ? tid - 14 : tid;
        const int  p   = s >> 1;
        const int  i   = s & 1;
        const float start = isy ? y1 : x1;
        const float rs    = isy ? roi_h : roi_w;
        const float bs    = rs * (1.0f / POOLED);
        const int   gq    = (int)ceilf(rs * (1.0f / POOLED));
        const float coord = start + (float)p * bs + ((float)i + 0.5f) * bs / (float)gq;

        const bool valid = (coord >= -1.0f) && (coord <= 128.0f);
        float cc = fmaxf(coord, 0.0f);
        int lo = min((int)cc, 127);
        int hi = min(lo + 1, 127);
        float l = (lo >= 127) ? 0.0f : (cc - (float)lo);
        float h = 1.0f - l;
        if (!valid) { l = 0.0f; h = 0.0f; }   // zero both factors -> sample = 0
        if (isy) { syl[s] = lo; syh[s] = hi; sly[s] = l; shy[s] = h; }
        else     { sxl[s] = lo; sxh[s] = hi; slx[s] = l; shx[s] = h; }
    }
    __syncthreads();

    const int b = (int)__ldg(boxes + k * 5 + 0);
    const float roi_w = fmaxf((__ldg(boxes + k*5+3) - __ldg(boxes + k*5+1)) * 0.25f, 1.0f);
    const float roi_h = fmaxf((__ldg(boxes + k*5+4) - __ldg(boxes + k*5+2)) * 0.25f, 1.0f);
    const int gw2 = min((int)ceilf(roi_w * (1.0f / POOLED)), 2);
    const int gh2 = min((int)ceilf(roi_h * (1.0f / POOLED)), 2);

    const float* base = g_tfeat + (size_t)b * (HWSZ * CC) + 4 * c;

    // CTA-uniform dispatch to fully-unrolled specializations
    if (gh2 == 1) {
        if (gw2 == 1) roi_body<1,1>(g, c, base, sxl, sxh, slx, shx, syl, syh, sly, shy, so);
        else          roi_body<1,2>(g, c, base, sxl, sxh, slx, shx, syl, syh, sly, shy, so);
    } else {
        if (gw2 == 1) roi_body<2,1>(g, c, base, sxl, sxh, slx, shx, syl, syh, sly, shy, so);
        else          roi_body<2,2>(g, c, base, sxl, sxh, slx, shx, syl, syh, sly, shy, so);
    }
    __syncthreads();

    // Coalesced write-out: out[k][ch][bin] = so[bin*PSTR + ch]
    float* dst = out + (size_t)k * PER_ROI;
#pragma unroll 7
    for (int i = tid; i < PER_ROI; i += 256) {
        const int ch  = i / NBIN;
        const int bin = i - ch * NBIN;
        dst[i] = so[bin * PSTR + ch];
    }
}

extern "C" void kernel_launch(void* const* d_in, const int* in_sizes, int n_in,
                              void* d_out, int out_size) {
    const float* features = (const float*)d_in[0];   // [4,256,128,128]
    const float* boxes    = (const float*)d_in[1];   // [1000,5]
    float* out = (float*)d_out;                      // [1000,256,7,7]
    (void)in_sizes; (void)n_in; (void)out_size;

    cudaFuncSetAttribute(roi_align_kernel,
                         cudaFuncAttributeMaxDynamicSharedMemorySize,
                         NBIN * PSTR * (int)sizeof(float));

    // 1) NCHW -> NHWC scratch
    dim3 gT(WW / 32, CC / 32, BB * HH);
    nchw_to_nhwc<<<gT, 256>>>(features);

    // 2) Fused gather + layout fix-up, one CTA per ROI
    roi_align_kernel<<<KK, 256, NBIN * PSTR * (int)sizeof(float)>>>(boxes, out);
}